// round 15
// baseline (speedup 1.0000x reference)
#include <cuda_runtime.h>
#include <cuda_fp16.h>
#include <cstdint>

// ---------------------------------------------------------------------------
// SparseResBlock on sm_103a — fp16 mma.sync m16n8k16, 128-row CTA tiles,
// RT=4 x NT=4 per warp, ldmatrix.x4 A-loads, 3-stage cp.async pipeline
// (compute k overlaps in-flight gather k+1 and issue of k+2).
// FIX vs r13: correct tail drain — wait_group<1> only valid while a younger
// group exists; last iteration (and K==1) must wait_group<0>.
//   h   = ReLU(BN1(spconv(x, W1, nbr1)))
//   h2  = BN2(spconv(h, W2, nbr2))
//   out = ReLU(h2 + BNd(x @ Wd))
// N=200000, Cin=64, Cout=128, K=27. Accumulation in fp32.
// (Round-15 resubmission of round-14 source: prior bench was an infra
//  failure — "GB300 container failed twice" — the kernel never executed.)
// ---------------------------------------------------------------------------

#define EPS_BN 1e-5f

constexpr int COUT   = 128;
constexpr int ROWS   = 128;       // output rows per CTA
constexpr int NTH    = 256;       // 8 warps: wr in {0,1} x wc in {0..3}
constexpr int NSTG   = 3;         // pipeline stages
constexpr int MAXN   = 200000;
constexpr int MAXBLK = (MAXN + ROWS - 1) / ROWS;   // 1563

// ---- device-global scratch (no allocation allowed in kernel_launch) ----
__device__ float  g_h1 [(size_t)MAXN * COUT];  // conv1 raw fp32
__device__ __half g_h1t[(size_t)MAXN * COUT];  // relu(BN1(h1)) fp16
__device__ float  g_h2 [(size_t)MAXN * COUT];  // conv2 raw fp32
__device__ float  g_sk [(size_t)MAXN * COUT];  // skip raw fp32
__device__ __half g_xt [(size_t)MAXN * 64];    // feats fp16
__device__ uint2  g_wp1[27 * 4 * 16 * 32];     // W1 frags (k16 chunks)
__device__ uint2  g_wp2[27 * 8 * 16 * 32];     // W2 frags
__device__ uint2  g_wpd[ 1 * 4 * 16 * 32];     // Wd frags
__device__ float g_part1[(size_t)MAXBLK * 256];
__device__ float g_part2[(size_t)MAXBLK * 256];
__device__ float g_partd[(size_t)MAXBLK * 256];
__device__ float g_sc1[COUT], g_sh1[COUT];
__device__ float g_sc2[COUT], g_sh2[COUT];
__device__ float g_scd[COUT], g_shd[COUT];

// ---------------------------------------------------------------------------
__device__ __forceinline__ uint32_t h2u(__half2 h) {
    return *reinterpret_cast<uint32_t*>(&h);
}

__device__ __forceinline__ void cp16(uint32_t dst, const void* src, int sz) {
    // cp.async 16B with runtime src-size (0 => zero-fill)
    asm volatile("cp.async.cg.shared.global [%0], [%1], 16, %2;\n"
                 :: "r"(dst), "l"(src), "r"(sz));
}
__device__ __forceinline__ void cp_commit() {
    asm volatile("cp.async.commit_group;\n" ::: "memory");
}
template<int N>
__device__ __forceinline__ void cp_wait() {
    asm volatile("cp.async.wait_group %0;\n" :: "n"(N) : "memory");
}

// ldmatrix x4 (b16): loads a full m16k16 fp16 A fragment in one op.
__device__ __forceinline__ void ldsm_x4(uint32_t& a0, uint32_t& a1,
                                        uint32_t& a2, uint32_t& a3,
                                        uint32_t addr) {
    asm volatile("ldmatrix.sync.aligned.m8n8.x4.shared.b16 "
                 "{%0,%1,%2,%3}, [%4];"
                 : "=r"(a0), "=r"(a1), "=r"(a2), "=r"(a3) : "r"(addr));
}

__device__ __forceinline__ void mma_f16(float acc[4],
                                        uint32_t a0, uint32_t a1,
                                        uint32_t a2, uint32_t a3,
                                        uint32_t b0, uint32_t b1) {
    asm volatile(
        "mma.sync.aligned.m16n8k16.row.col.f32.f16.f16.f32 "
        "{%0,%1,%2,%3}, {%4,%5,%6,%7}, {%8,%9}, {%0,%1,%2,%3};\n"
        : "+f"(acc[0]), "+f"(acc[1]), "+f"(acc[2]), "+f"(acc[3])
        : "r"(a0), "r"(a1), "r"(a2), "r"(a3), "r"(b0), "r"(b1));
}

// ---------------------------------------------------------------------------
// Weight reorder: W[K][CIN][128] -> m16n8k16 .row.col B fragments (fp16).
// uint2 at index ((k*KC + kc)*16 + nt)*32 + lane  (KC = CIN/16):
//   .x = half2{ W[kc*16 + 2tg    ][nt*8 + g], W[kc*16 + 2tg + 1][nt*8 + g] }
//   .y = half2{ W[kc*16 + 2tg + 8][nt*8 + g], W[kc*16 + 2tg + 9][nt*8 + g] }
// (tg = lane&3, g = lane>>2). One warp B-frag load = one coalesced LDG.64.
// ---------------------------------------------------------------------------
__global__ void prep_w(const float* __restrict__ W, uint2* __restrict__ Wp,
                       int K, int CIN)
{
    const int KC    = CIN / 16;
    const int total = K * KC * 16 * 32;
    const int gid   = blockIdx.x * blockDim.x + threadIdx.x;
    if (gid >= total) return;
    const int lane = gid & 31;
    const int tg = lane & 3, g = lane >> 2;
    int t  = gid >> 5;
    const int nt = t & 15;  t >>= 4;
    const int kc = t % KC;
    const int k  = t / KC;
    const int col = nt * 8 + g;
    const size_t b = ((size_t)k * CIN + kc * 16 + 2 * tg) * COUT + col;
    uint2 v;
    v.x = h2u(__floats2half2_rn(W[b],            W[b + COUT]));
    v.y = h2u(__floats2half2_rn(W[b + 8 * COUT], W[b + 9 * COUT]));
    Wp[gid] = v;
}

// elementwise: y = fp16(x), 8 elements per thread
__global__ void cvt_h(const float* __restrict__ x, __half* __restrict__ y,
                      int total8)
{
    const int i = blockIdx.x * blockDim.x + threadIdx.x;
    if (i >= total8) return;
    const float4 f0 = reinterpret_cast<const float4*>(x)[2 * i];
    const float4 f1 = reinterpret_cast<const float4*>(x)[2 * i + 1];
    uint4 o;
    o.x = h2u(__floats2half2_rn(f0.x, f0.y));
    o.y = h2u(__floats2half2_rn(f0.z, f0.w));
    o.z = h2u(__floats2half2_rn(f1.x, f1.y));
    o.w = h2u(__floats2half2_rn(f1.z, f1.w));
    reinterpret_cast<uint4*>(y)[i] = o;
}

// elementwise: y = fp16(relu(x*sc + sh)), per-channel sc/sh (COUT=128)
__global__ void bn_relu_cvt_h(const float* __restrict__ x,
                              const float* __restrict__ sc,
                              const float* __restrict__ sh,
                              __half* __restrict__ y, int total8)
{
    const int i = blockIdx.x * blockDim.x + threadIdx.x;
    if (i >= total8) return;
    const int c = i & 15;                    // 8-channel group
    const float4 f0 = reinterpret_cast<const float4*>(x)[2 * i];
    const float4 f1 = reinterpret_cast<const float4*>(x)[2 * i + 1];
    const float4 s0 = reinterpret_cast<const float4*>(sc)[2 * c];
    const float4 s1 = reinterpret_cast<const float4*>(sc)[2 * c + 1];
    const float4 t0 = reinterpret_cast<const float4*>(sh)[2 * c];
    const float4 t1 = reinterpret_cast<const float4*>(sh)[2 * c + 1];
    uint4 o;
    o.x = h2u(__floats2half2_rn(fmaxf(0.f, fmaf(f0.x, s0.x, t0.x)),
                                fmaxf(0.f, fmaf(f0.y, s0.y, t0.y))));
    o.y = h2u(__floats2half2_rn(fmaxf(0.f, fmaf(f0.z, s0.z, t0.z)),
                                fmaxf(0.f, fmaf(f0.w, s0.w, t0.w))));
    o.z = h2u(__floats2half2_rn(fmaxf(0.f, fmaf(f1.x, s1.x, t1.x)),
                                fmaxf(0.f, fmaf(f1.y, s1.y, t1.y))));
    o.w = h2u(__floats2half2_rn(fmaxf(0.f, fmaf(f1.z, s1.z, t1.z)),
                                fmaxf(0.f, fmaf(f1.w, s1.w, t1.w))));
    reinterpret_cast<uint4*>(y)[i] = o;
}

// ---------------------------------------------------------------------------
// fp16 tensor-core gather-GEMM. CTA: 128 rows x 128 cols. 8 warps:
//   wr = warp&1  -> rows [wr*64, +64)  (FOUR m16 tiles via ldmatrix.x4)
//   wc = warp>>1 -> cols [wc*32, +32)  (four n8 tiles)
// 3-stage cp.async pipeline: compute buf k while gather k+1 is in flight
// and k+2 is being issued. Tail drain: wait_group<0> once no younger
// group exists (k+1 >= K) — required for correctness.
// ROW_B = (CIN+8)*2 bytes => ldmatrix rows land 4 banks apart: conflict-free.
// Emits per-channel (Sx, Sx^2) BN partials (fp32 accumulators).
// ---------------------------------------------------------------------------
template<int CIN>
__global__ __launch_bounds__(NTH, 2)
void conv_mma(const __half* __restrict__ X,    // [n, CIN] fp16
              const uint2*  __restrict__ Wp,   // fragment-ordered weights
              const int*    __restrict__ nbr,  // [K, n] or nullptr (identity)
              int K, int n,
              float* __restrict__ out,         // [n, COUT] fp32
              float* __restrict__ partial)     // [nb, 256] (Sx | Sxx)
{
    constexpr int V     = CIN / 8;             // 16B units per row
    constexpr int ROW_B = (CIN + 8) * 2;       // padded SMEM row bytes
    constexpr int KC    = CIN / 16;            // k16 chunks
    constexpr int BUF_B = ROWS * ROW_B;        // bytes per stage
    extern __shared__ char smem[];             // [NSTG][BUF_B]

    const int tid  = threadIdx.x;
    const int lane = tid & 31, warp = tid >> 5;
    const int wr   = warp & 1,  wc  = warp >> 1;
    const int g    = lane >> 2, tg  = lane & 3;
    const int base = blockIdx.x * ROWS;
    const uint32_t sbase = (uint32_t)__cvta_generic_to_shared(smem);

    // per-lane ldmatrix address (t=0, kc=0, buffer 0)
    const int mat = lane >> 3, mr = lane & 7;
    const uint32_t lds0 = sbase +
        (uint32_t)((wr * 64 + (mat & 1) * 8 + mr) * ROW_B + (mat >> 1) * 16);

    float acc[4][4][4];                        // [row tile][n tile][frag]
#pragma unroll
    for (int t = 0; t < 4; ++t)
#pragma unroll
        for (int p = 0; p < 4; ++p)
#pragma unroll
            for (int j = 0; j < 4; ++j) acc[t][p][j] = 0.f;

    // -- async gather of offset k into buffer (k % NSTG); zero-fill missing --
    auto issue = [&](int k) {
        const uint32_t dst0 = sbase + (uint32_t)((k % NSTG) * BUF_B);
#pragma unroll
        for (int i = 0; i < ROWS * V / NTH; ++i) {
            const int e   = tid + i * NTH;
            const int r   = e / V;
            const int c8  = e - r * V;
            const int row = base + r;
            int idx = -1;
            if (row < n)
                idx = nbr ? __ldg(&nbr[(size_t)k * n + row]) : row;
            const __half* src = X + (size_t)(idx < 0 ? 0 : idx) * CIN + c8 * 8;
            cp16(dst0 + (uint32_t)(r * ROW_B + c8 * 16), src,
                 idx >= 0 ? 16 : 0);
        }
        cp_commit();
    };

    issue(0);
    if (K > 1) issue(1);

    for (int k = 0; k < K; ++k) {
        // pending groups here: {k, ..., min(k+1, K-1)}. A younger group
        // (k+1) exists iff k+1 < K; only then may we leave one in flight.
        if (k + 1 < K) cp_wait<1>(); else cp_wait<0>();
        __syncthreads();                 // buf k%NSTG visible; buf (k+2)%NSTG
                                         // (last read at compute k-1) free
        if (k + 2 < K) issue(k + 2);

        const uint32_t abase = lds0 + (uint32_t)((k % NSTG) * BUF_B);
#pragma unroll
        for (int kc = 0; kc < KC; ++kc) {
            uint32_t a[4][4];
#pragma unroll
            for (int t = 0; t < 4; ++t)
                ldsm_x4(a[t][0], a[t][1], a[t][2], a[t][3],
                        abase + (uint32_t)(t * 16 * ROW_B + kc * 32));
            const uint2* Bk = Wp + ((size_t)(k * KC + kc) * 16 + wc * 4) * 32
                            + lane;
#pragma unroll
            for (int p = 0; p < 4; ++p) {
                const uint2 bv = __ldg(&Bk[p * 32]);
#pragma unroll
                for (int t = 0; t < 4; ++t)
                    mma_f16(acc[t][p], a[t][0], a[t][1], a[t][2], a[t][3],
                            bv.x, bv.y);
            }
        }
    }

    // ---- store conv output (fp32) ----
#pragma unroll
    for (int t = 0; t < 4; ++t) {
        const int row = base + wr * 64 + t * 16 + g;
#pragma unroll
        for (int p = 0; p < 4; ++p) {
            const int col = wc * 32 + p * 8 + 2 * tg;
            if (row < n)
                *reinterpret_cast<float2*>(out + (size_t)row * COUT + col) =
                    make_float2(acc[t][p][0], acc[t][p][1]);
            if (row + 8 < n)
                *reinterpret_cast<float2*>(out + (size_t)(row + 8) * COUT + col) =
                    make_float2(acc[t][p][2], acc[t][p][3]);
        }
    }

    // ---- deterministic per-channel partials (Sx, Sx^2) ----
    float s[4][2], q[4][2];
#pragma unroll
    for (int p = 0; p < 4; ++p)
#pragma unroll
        for (int j = 0; j < 2; ++j) {
            float ss = 0.f, qq = 0.f;
#pragma unroll
            for (int t = 0; t < 4; ++t) {
                ss += acc[t][p][j] + acc[t][p][j + 2];
                qq += acc[t][p][j]     * acc[t][p][j]
                    + acc[t][p][j + 2] * acc[t][p][j + 2];
            }
            s[p][j] = ss; q[p][j] = qq;
        }
#pragma unroll
    for (int off = 4; off <= 16; off <<= 1)      // reduce over g (8 lanes)
#pragma unroll
        for (int p = 0; p < 4; ++p)
#pragma unroll
            for (int j = 0; j < 2; ++j) {
                s[p][j] += __shfl_xor_sync(0xffffffffu, s[p][j], off);
                q[p][j] += __shfl_xor_sync(0xffffffffu, q[p][j], off);
            }

    __syncthreads();                              // everyone done with smem
    float* sS = reinterpret_cast<float*>(smem);   // [wr:2][128]
    float* sQ = sS + 256;                         // [wr:2][128]
    if (lane < 4) {                               // g == 0 lanes (tg = lane)
#pragma unroll
        for (int p = 0; p < 4; ++p) {
            const int col = wc * 32 + p * 8 + 2 * tg;
            sS[wr * 128 + col]     = s[p][0];
            sS[wr * 128 + col + 1] = s[p][1];
            sQ[wr * 128 + col]     = q[p][0];
            sQ[wr * 128 + col + 1] = q[p][1];
        }
    }
    __syncthreads();
    if (tid < 128) {
        partial[(size_t)blockIdx.x * 256 + tid] = sS[tid] + sS[128 + tid];
    } else {
        const int c = tid - 128;
        partial[(size_t)blockIdx.x * 256 + 128 + c] = sQ[c] + sQ[128 + c];
    }
}

// ---------------------------------------------------------------------------
// Parallel BN finalize: 128 blocks (one per channel) x 256 threads.
// ---------------------------------------------------------------------------
__global__ void bn_finalize(const float* __restrict__ partial, int nb, int n,
                            const float* __restrict__ gamma,
                            const float* __restrict__ beta,
                            float* __restrict__ scale,
                            float* __restrict__ shift)
{
    const int c = blockIdx.x;
    const int t = threadIdx.x;
    __shared__ double rS[256], rQ[256];
    double S = 0.0, Q = 0.0;
    for (int b = t; b < nb; b += 256) {
        S += (double)partial[(size_t)b * 256 + c];
        Q += (double)partial[(size_t)b * 256 + 128 + c];
    }
    rS[t] = S; rQ[t] = Q;
    __syncthreads();
    for (int off = 128; off > 0; off >>= 1) {
        if (t < off) { rS[t] += rS[t + off]; rQ[t] += rQ[t + off]; }
        __syncthreads();
    }
    if (t == 0) {
        const double mean = rS[0] / n;
        const double var  = rQ[0] / n - mean * mean;
        const float  r    = rsqrtf((float)var + EPS_BN);
        const float  sc   = gamma[c] * r;
        scale[c] = sc;
        shift[c] = beta[c] - (float)mean * sc;
    }
}

// out = relu( h2*sc2 + sh2 + sk*scd + shd )
__global__ void final_kernel(const float* __restrict__ h2,
                             const float* __restrict__ sk,
                             const float* __restrict__ sc2,
                             const float* __restrict__ sh2,
                             const float* __restrict__ scd,
                             const float* __restrict__ shd,
                             float* __restrict__ out, int total4)
{
    const int i = blockIdx.x * blockDim.x + threadIdx.x;
    if (i >= total4) return;
    const int c4 = i & 31;
    const float4 a  = reinterpret_cast<const float4*>(h2)[i];
    const float4 b  = reinterpret_cast<const float4*>(sk)[i];
    const float4 s2 = reinterpret_cast<const float4*>(sc2)[c4];
    const float4 t2 = reinterpret_cast<const float4*>(sh2)[c4];
    const float4 sd = reinterpret_cast<const float4*>(scd)[c4];
    const float4 td = reinterpret_cast<const float4*>(shd)[c4];
    float4 v;
    v.x = fmaxf(0.f, fmaf(a.x, s2.x, t2.x) + fmaf(b.x, sd.x, td.x));
    v.y = fmaxf(0.f, fmaf(a.y, s2.y, t2.y) + fmaf(b.y, sd.y, td.y));
    v.z = fmaxf(0.f, fmaf(a.z, s2.z, t2.z) + fmaf(b.z, sd.z, td.z));
    v.w = fmaxf(0.f, fmaf(a.w, s2.w, t2.w) + fmaf(b.w, sd.w, td.w));
    reinterpret_cast<float4*>(out)[i] = v;
}

// ---------------------------------------------------------------------------
extern "C" void kernel_launch(void* const* d_in, const int* in_sizes, int n_in,
                              void* d_out, int out_size)
{
    const float* feats = (const float*)d_in[0];
    const int*   nbr1  = (const int*)  d_in[1];
    const int*   nbr2  = (const int*)  d_in[2];
    const float* W1    = (const float*)d_in[3];
    const float* W2    = (const float*)d_in[4];
    const float* Wd    = (const float*)d_in[5];
    const float* g1    = (const float*)d_in[6];
    const float* b1    = (const float*)d_in[7];
    const float* g2    = (const float*)d_in[8];
    const float* b2    = (const float*)d_in[9];
    const float* gd    = (const float*)d_in[10];
    const float* bd    = (const float*)d_in[11];
    float* out = (float*)d_out;

    const int n  = in_sizes[0] / 64;      // 200000
    const int K  = in_sizes[1] / n;       // 27
    const int nb = (n + ROWS - 1) / ROWS; // 1563

    float *h1, *h2, *sk, *p1, *p2, *pd;
    __half *h1t, *xt;
    uint2 *wp1, *wp2, *wpd;
    float *sc1, *sh1, *sc2, *sh2, *scd, *shd;
    cudaGetSymbolAddress((void**)&h1,  g_h1);
    cudaGetSymbolAddress((void**)&h1t, g_h1t);
    cudaGetSymbolAddress((void**)&h2,  g_h2);
    cudaGetSymbolAddress((void**)&sk,  g_sk);
    cudaGetSymbolAddress((void**)&xt,  g_xt);
    cudaGetSymbolAddress((void**)&wp1, g_wp1);
    cudaGetSymbolAddress((void**)&wp2, g_wp2);
    cudaGetSymbolAddress((void**)&wpd, g_wpd);
    cudaGetSymbolAddress((void**)&p1,  g_part1);
    cudaGetSymbolAddress((void**)&p2,  g_part2);
    cudaGetSymbolAddress((void**)&pd,  g_partd);
    cudaGetSymbolAddress((void**)&sc1, g_sc1);
    cudaGetSymbolAddress((void**)&sh1, g_sh1);
    cudaGetSymbolAddress((void**)&sc2, g_sc2);
    cudaGetSymbolAddress((void**)&sh2, g_sh2);
    cudaGetSymbolAddress((void**)&scd, g_scd);
    cudaGetSymbolAddress((void**)&shd, g_shd);

    const int smem64  = NSTG * ROWS * (64 + 8)  * 2;   //  55296 B
    const int smem128 = NSTG * ROWS * (128 + 8) * 2;   // 104448 B
    cudaFuncSetAttribute(conv_mma<64>,
        cudaFuncAttributeMaxDynamicSharedMemorySize, smem64);
    cudaFuncSetAttribute(conv_mma<128>,
        cudaFuncAttributeMaxDynamicSharedMemorySize, smem128);

    // ---- prep (ordered so ncu capture at launch index 3 hits conv1) ----
    const int xt8 = n * (64 / 8);
    cvt_h<<<(xt8 + 255) / 256, 256>>>(feats, xt, xt8);               // 0
    {
        int t1 = K * (64 / 16)  * 16 * 32;
        int t2 = K * (128 / 16) * 16 * 32;
        prep_w<<<(t1 + 255) / 256, 256>>>(W1, wp1, K, 64);           // 1
        prep_w<<<(t2 + 255) / 256, 256>>>(W2, wp2, K, 128);          // 2
    }
    // conv1 + BN1 partials                                          // 3
    conv_mma<64><<<nb, NTH, smem64>>>(xt, wp1, nbr1, K, n, h1, p1);
    {
        int td = 1 * (64 / 16) * 16 * 32;
        prep_w<<<(td + 255) / 256, 256>>>(Wd, wpd, 1, 64);
    }
    // skip (identity gather, K=1) + BNd partials
    conv_mma<64><<<nb, NTH, smem64>>>(xt, wpd, nullptr, 1, n, sk, pd);
    bn_finalize<<<128, 256>>>(p1, nb, n, g1, b1, sc1, sh1);
    bn_finalize<<<128, 256>>>(pd, nb, n, gd, bd, scd, shd);
    // h1t = fp16(relu(BN1(h1)))
    const int t8 = n * (COUT / 8);
    bn_relu_cvt_h<<<(t8 + 255) / 256, 256>>>(h1, sc1, sh1, h1t, t8);
    // conv2 + BN2 partials
    conv_mma<128><<<nb, NTH, smem128>>>(h1t, wp2, nbr2, K, n, h2, p2);
    bn_finalize<<<128, 256>>>(p2, nb, n, g2, b2, sc2, sh2);
    // out = relu(BN2(h2) + BNd(sk))
    const int t4 = n * (COUT / 4);
    final_kernel<<<(t4 + 255) / 256, 256>>>(h2, sk, sc2, sh2,
                                            scd, shd, out, t4);
}

// round 17
// speedup vs baseline: 1.1698x; 1.1698x over previous
#include <cuda_runtime.h>
#include <cuda_fp16.h>
#include <cstdint>

// ---------------------------------------------------------------------------
// SparseResBlock on sm_103a — fp16 mma.sync m16n8k16, 128-row CTA tiles,
// RT=4 x NT=4 per warp, ldmatrix.x4 A-loads, double-buffered cp.async gather,
// and EXPLICIT B-fragment prefetch (kc+1 loaded during kc's mmas; kc=0 loaded
// across the k-boundary barrier). Inner loop is t-outer so only one A frag
// is live => regs ~105 < 128 cap, giving ptxas room to schedule the loads.
//   h   = ReLU(BN1(spconv(x, W1, nbr1)))
//   h2  = BN2(spconv(h, W2, nbr2))
//   out = ReLU(h2 + BNd(x @ Wd))
// N=200000, Cin=64, Cout=128, K=27. Accumulation in fp32.
// ---------------------------------------------------------------------------

#define EPS_BN 1e-5f

constexpr int COUT   = 128;
constexpr int ROWS   = 128;       // output rows per CTA
constexpr int NTH    = 256;       // 8 warps: wr in {0,1} x wc in {0..3}
constexpr int MAXN   = 200000;
constexpr int MAXBLK = (MAXN + ROWS - 1) / ROWS;   // 1563

// ---- device-global scratch (no allocation allowed in kernel_launch) ----
__device__ float  g_h1 [(size_t)MAXN * COUT];  // conv1 raw fp32
__device__ __half g_h1t[(size_t)MAXN * COUT];  // relu(BN1(h1)) fp16
__device__ float  g_h2 [(size_t)MAXN * COUT];  // conv2 raw fp32
__device__ float  g_sk [(size_t)MAXN * COUT];  // skip raw fp32
__device__ __half g_xt [(size_t)MAXN * 64];    // feats fp16
__device__ uint2  g_wp1[27 * 4 * 16 * 32];     // W1 frags (k16 chunks)
__device__ uint2  g_wp2[27 * 8 * 16 * 32];     // W2 frags
__device__ uint2  g_wpd[ 1 * 4 * 16 * 32];     // Wd frags
__device__ float g_part1[(size_t)MAXBLK * 256];
__device__ float g_part2[(size_t)MAXBLK * 256];
__device__ float g_partd[(size_t)MAXBLK * 256];
__device__ float g_sc1[COUT], g_sh1[COUT];
__device__ float g_sc2[COUT], g_sh2[COUT];
__device__ float g_scd[COUT], g_shd[COUT];

// ---------------------------------------------------------------------------
__device__ __forceinline__ uint32_t h2u(__half2 h) {
    return *reinterpret_cast<uint32_t*>(&h);
}

__device__ __forceinline__ void cp16(uint32_t dst, const void* src, int sz) {
    // cp.async 16B with runtime src-size (0 => zero-fill)
    asm volatile("cp.async.cg.shared.global [%0], [%1], 16, %2;\n"
                 :: "r"(dst), "l"(src), "r"(sz));
}
__device__ __forceinline__ void cp_commit() {
    asm volatile("cp.async.commit_group;\n" ::: "memory");
}
__device__ __forceinline__ void cp_wait_all() {
    asm volatile("cp.async.wait_group 0;\n" ::: "memory");
}

// ldmatrix x4 (b16): loads a full m16k16 fp16 A fragment in one op.
__device__ __forceinline__ void ldsm_x4(uint32_t& a0, uint32_t& a1,
                                        uint32_t& a2, uint32_t& a3,
                                        uint32_t addr) {
    asm volatile("ldmatrix.sync.aligned.m8n8.x4.shared.b16 "
                 "{%0,%1,%2,%3}, [%4];"
                 : "=r"(a0), "=r"(a1), "=r"(a2), "=r"(a3) : "r"(addr));
}

__device__ __forceinline__ void mma_f16(float acc[4],
                                        uint32_t a0, uint32_t a1,
                                        uint32_t a2, uint32_t a3,
                                        uint32_t b0, uint32_t b1) {
    asm volatile(
        "mma.sync.aligned.m16n8k16.row.col.f32.f16.f16.f32 "
        "{%0,%1,%2,%3}, {%4,%5,%6,%7}, {%8,%9}, {%0,%1,%2,%3};\n"
        : "+f"(acc[0]), "+f"(acc[1]), "+f"(acc[2]), "+f"(acc[3])
        : "r"(a0), "r"(a1), "r"(a2), "r"(a3), "r"(b0), "r"(b1));
}

// ---------------------------------------------------------------------------
// Weight reorder: W[K][CIN][128] -> m16n8k16 .row.col B fragments (fp16).
// uint2 at index ((k*KC + kc)*16 + nt)*32 + lane  (KC = CIN/16):
//   .x = half2{ W[kc*16 + 2tg    ][nt*8 + g], W[kc*16 + 2tg + 1][nt*8 + g] }
//   .y = half2{ W[kc*16 + 2tg + 8][nt*8 + g], W[kc*16 + 2tg + 9][nt*8 + g] }
// (tg = lane&3, g = lane>>2). One warp B-frag load = one coalesced LDG.64.
// ---------------------------------------------------------------------------
__global__ void prep_w(const float* __restrict__ W, uint2* __restrict__ Wp,
                       int K, int CIN)
{
    const int KC    = CIN / 16;
    const int total = K * KC * 16 * 32;
    const int gid   = blockIdx.x * blockDim.x + threadIdx.x;
    if (gid >= total) return;
    const int lane = gid & 31;
    const int tg = lane & 3, g = lane >> 2;
    int t  = gid >> 5;
    const int nt = t & 15;  t >>= 4;
    const int kc = t % KC;
    const int k  = t / KC;
    const int col = nt * 8 + g;
    const size_t b = ((size_t)k * CIN + kc * 16 + 2 * tg) * COUT + col;
    uint2 v;
    v.x = h2u(__floats2half2_rn(W[b],            W[b + COUT]));
    v.y = h2u(__floats2half2_rn(W[b + 8 * COUT], W[b + 9 * COUT]));
    Wp[gid] = v;
}

// elementwise: y = fp16(x), 8 elements per thread
__global__ void cvt_h(const float* __restrict__ x, __half* __restrict__ y,
                      int total8)
{
    const int i = blockIdx.x * blockDim.x + threadIdx.x;
    if (i >= total8) return;
    const float4 f0 = reinterpret_cast<const float4*>(x)[2 * i];
    const float4 f1 = reinterpret_cast<const float4*>(x)[2 * i + 1];
    uint4 o;
    o.x = h2u(__floats2half2_rn(f0.x, f0.y));
    o.y = h2u(__floats2half2_rn(f0.z, f0.w));
    o.z = h2u(__floats2half2_rn(f1.x, f1.y));
    o.w = h2u(__floats2half2_rn(f1.z, f1.w));
    reinterpret_cast<uint4*>(y)[i] = o;
}

// elementwise: y = fp16(relu(x*sc + sh)), per-channel sc/sh (COUT=128)
__global__ void bn_relu_cvt_h(const float* __restrict__ x,
                              const float* __restrict__ sc,
                              const float* __restrict__ sh,
                              __half* __restrict__ y, int total8)
{
    const int i = blockIdx.x * blockDim.x + threadIdx.x;
    if (i >= total8) return;
    const int c = i & 15;                    // 8-channel group
    const float4 f0 = reinterpret_cast<const float4*>(x)[2 * i];
    const float4 f1 = reinterpret_cast<const float4*>(x)[2 * i + 1];
    const float4 s0 = reinterpret_cast<const float4*>(sc)[2 * c];
    const float4 s1 = reinterpret_cast<const float4*>(sc)[2 * c + 1];
    const float4 t0 = reinterpret_cast<const float4*>(sh)[2 * c];
    const float4 t1 = reinterpret_cast<const float4*>(sh)[2 * c + 1];
    uint4 o;
    o.x = h2u(__floats2half2_rn(fmaxf(0.f, fmaf(f0.x, s0.x, t0.x)),
                                fmaxf(0.f, fmaf(f0.y, s0.y, t0.y))));
    o.y = h2u(__floats2half2_rn(fmaxf(0.f, fmaf(f0.z, s0.z, t0.z)),
                                fmaxf(0.f, fmaf(f0.w, s0.w, t0.w))));
    o.z = h2u(__floats2half2_rn(fmaxf(0.f, fmaf(f1.x, s1.x, t1.x)),
                                fmaxf(0.f, fmaf(f1.y, s1.y, t1.y))));
    o.w = h2u(__floats2half2_rn(fmaxf(0.f, fmaf(f1.z, s1.z, t1.z)),
                                fmaxf(0.f, fmaf(f1.w, s1.w, t1.w))));
    reinterpret_cast<uint4*>(y)[i] = o;
}

// ---------------------------------------------------------------------------
// fp16 tensor-core gather-GEMM. CTA: 128 rows x 128 cols. 8 warps:
//   wr = warp&1  -> rows [wr*64, +64)  (FOUR m16 tiles via ldmatrix.x4)
//   wc = warp>>1 -> cols [wc*32, +32)  (four n8 tiles)
// Double-buffered cp.async gather. B fragments explicitly prefetched:
// kc=0's frags load BEFORE the k-boundary barrier (independent of smem),
// kc+1's frags load before kc's mma block. t-outer mma loop keeps only one
// A fragment live (regs ~105 < 128 cap => no spill, schedulable loads).
// Emits per-channel (Sx, Sx^2) BN partials (fp32 accumulators).
// ---------------------------------------------------------------------------
template<int CIN>
__global__ __launch_bounds__(NTH, 2)
void conv_mma(const __half* __restrict__ X,    // [n, CIN] fp16
              const uint2*  __restrict__ Wp,   // fragment-ordered weights
              const int*    __restrict__ nbr,  // [K, n] or nullptr (identity)
              int K, int n,
              float* __restrict__ out,         // [n, COUT] fp32
              float* __restrict__ partial)     // [nb, 256] (Sx | Sxx)
{
    constexpr int V     = CIN / 8;             // 16B units per row
    constexpr int ROW_B = (CIN + 8) * 2;       // padded SMEM row bytes
    constexpr int KC    = CIN / 16;            // k16 chunks
    constexpr int BUF_B = ROWS * ROW_B;        // bytes per stage
    extern __shared__ char smem[];             // [2][BUF_B]

    const int tid  = threadIdx.x;
    const int lane = tid & 31, warp = tid >> 5;
    const int wr   = warp & 1,  wc  = warp >> 1;
    const int g    = lane >> 2, tg  = lane & 3;
    const int base = blockIdx.x * ROWS;
    const uint32_t sbase = (uint32_t)__cvta_generic_to_shared(smem);

    // per-lane ldmatrix address (t=0, kc=0, buffer 0)
    const int mat = lane >> 3, mr = lane & 7;
    const uint32_t lds0 = sbase +
        (uint32_t)((wr * 64 + (mat & 1) * 8 + mr) * ROW_B + (mat >> 1) * 16);

    float acc[4][4][4];                        // [row tile][n tile][frag]
#pragma unroll
    for (int t = 0; t < 4; ++t)
#pragma unroll
        for (int p = 0; p < 4; ++p)
#pragma unroll
            for (int j = 0; j < 4; ++j) acc[t][p][j] = 0.f;

    // -- async gather of offset k into buffer (k&1); zero-fill missing --
    auto issue = [&](int k) {
        const uint32_t dst0 = sbase + (uint32_t)((k & 1) * BUF_B);
#pragma unroll
        for (int i = 0; i < ROWS * V / NTH; ++i) {
            const int e   = tid + i * NTH;
            const int r   = e / V;
            const int c8  = e - r * V;
            const int row = base + r;
            int idx = -1;
            if (row < n)
                idx = nbr ? __ldg(&nbr[(size_t)k * n + row]) : row;
            const __half* src = X + (size_t)(idx < 0 ? 0 : idx) * CIN + c8 * 8;
            cp16(dst0 + (uint32_t)(r * ROW_B + c8 * 16), src,
                 idx >= 0 ? 16 : 0);
        }
        cp_commit();
    };

    issue(0);

    for (int k = 0; k < K; ++k) {
        // B frags for kc=0: pure global reads, independent of the gather —
        // issue BEFORE the wait/barrier so the LDG latency overlaps it.
        const uint2* Bk0 = Wp + ((size_t)k * KC * 16 + wc * 4) * 32 + lane;
        uint2 bv[4];
#pragma unroll
        for (int p = 0; p < 4; ++p) bv[p] = __ldg(&Bk0[p * 32]);

        cp_wait_all();
        __syncthreads();                 // buf k&1 ready
        if (k + 1 < K) issue(k + 1);     // overlap next gather with compute

        const uint32_t abase = lds0 + (uint32_t)((k & 1) * BUF_B);
#pragma unroll
        for (int kc = 0; kc < KC; ++kc) {
            // prefetch kc+1's B frags before this chunk's mmas
            uint2 bvn[4];
            if (kc + 1 < KC) {
                const uint2* Bkn = Bk0 + (size_t)(kc + 1) * 16 * 32;
#pragma unroll
                for (int p = 0; p < 4; ++p) bvn[p] = __ldg(&Bkn[p * 32]);
            }
            // t-outer: only one A fragment live at a time
#pragma unroll
            for (int t = 0; t < 4; ++t) {
                uint32_t a0, a1, a2, a3;
                ldsm_x4(a0, a1, a2, a3,
                        abase + (uint32_t)(t * 16 * ROW_B + kc * 32));
#pragma unroll
                for (int p = 0; p < 4; ++p)
                    mma_f16(acc[t][p], a0, a1, a2, a3, bv[p].x, bv[p].y);
            }
            if (kc + 1 < KC) {
#pragma unroll
                for (int p = 0; p < 4; ++p) bv[p] = bvn[p];
            }
        }
    }

    // ---- store conv output (fp32) ----
#pragma unroll
    for (int t = 0; t < 4; ++t) {
        const int row = base + wr * 64 + t * 16 + g;
#pragma unroll
        for (int p = 0; p < 4; ++p) {
            const int col = wc * 32 + p * 8 + 2 * tg;
            if (row < n)
                *reinterpret_cast<float2*>(out + (size_t)row * COUT + col) =
                    make_float2(acc[t][p][0], acc[t][p][1]);
            if (row + 8 < n)
                *reinterpret_cast<float2*>(out + (size_t)(row + 8) * COUT + col) =
                    make_float2(acc[t][p][2], acc[t][p][3]);
        }
    }

    // ---- deterministic per-channel partials (Sx, Sx^2) ----
    float s[4][2], q[4][2];
#pragma unroll
    for (int p = 0; p < 4; ++p)
#pragma unroll
        for (int j = 0; j < 2; ++j) {
            float ss = 0.f, qq = 0.f;
#pragma unroll
            for (int t = 0; t < 4; ++t) {
                ss += acc[t][p][j] + acc[t][p][j + 2];
                qq += acc[t][p][j]     * acc[t][p][j]
                    + acc[t][p][j + 2] * acc[t][p][j + 2];
            }
            s[p][j] = ss; q[p][j] = qq;
        }
#pragma unroll
    for (int off = 4; off <= 16; off <<= 1)      // reduce over g (8 lanes)
#pragma unroll
        for (int p = 0; p < 4; ++p)
#pragma unroll
            for (int j = 0; j < 2; ++j) {
                s[p][j] += __shfl_xor_sync(0xffffffffu, s[p][j], off);
                q[p][j] += __shfl_xor_sync(0xffffffffu, q[p][j], off);
            }

    __syncthreads();                              // everyone done with smem
    float* sS = reinterpret_cast<float*>(smem);   // [wr:2][128]
    float* sQ = sS + 256;                         // [wr:2][128]
    if (lane < 4) {                               // g == 0 lanes (tg = lane)
#pragma unroll
        for (int p = 0; p < 4; ++p) {
            const int col = wc * 32 + p * 8 + 2 * tg;
            sS[wr * 128 + col]     = s[p][0];
            sS[wr * 128 + col + 1] = s[p][1];
            sQ[wr * 128 + col]     = q[p][0];
            sQ[wr * 128 + col + 1] = q[p][1];
        }
    }
    __syncthreads();
    if (tid < 128) {
        partial[(size_t)blockIdx.x * 256 + tid] = sS[tid] + sS[128 + tid];
    } else {
        const int c = tid - 128;
        partial[(size_t)blockIdx.x * 256 + 128 + c] = sQ[c] + sQ[128 + c];
    }
}

// ---------------------------------------------------------------------------
// Parallel BN finalize: 128 blocks (one per channel) x 256 threads.
// ---------------------------------------------------------------------------
__global__ void bn_finalize(const float* __restrict__ partial, int nb, int n,
                            const float* __restrict__ gamma,
                            const float* __restrict__ beta,
                            float* __restrict__ scale,
                            float* __restrict__ shift)
{
    const int c = blockIdx.x;
    const int t = threadIdx.x;
    __shared__ double rS[256], rQ[256];
    double S = 0.0, Q = 0.0;
    for (int b = t; b < nb; b += 256) {
        S += (double)partial[(size_t)b * 256 + c];
        Q += (double)partial[(size_t)b * 256 + 128 + c];
    }
    rS[t] = S; rQ[t] = Q;
    __syncthreads();
    for (int off = 128; off > 0; off >>= 1) {
        if (t < off) { rS[t] += rS[t + off]; rQ[t] += rQ[t + off]; }
        __syncthreads();
    }
    if (t == 0) {
        const double mean = rS[0] / n;
        const double var  = rQ[0] / n - mean * mean;
        const float  r    = rsqrtf((float)var + EPS_BN);
        const float  sc   = gamma[c] * r;
        scale[c] = sc;
        shift[c] = beta[c] - (float)mean * sc;
    }
}

// out = relu( h2*sc2 + sh2 + sk*scd + shd )
__global__ void final_kernel(const float* __restrict__ h2,
                             const float* __restrict__ sk,
                             const float* __restrict__ sc2,
                             const float* __restrict__ sh2,
                             const float* __restrict__ scd,
                             const float* __restrict__ shd,
                             float* __restrict__ out, int total4)
{
    const int i = blockIdx.x * blockDim.x + threadIdx.x;
    if (i >= total4) return;
    const int c4 = i & 31;
    const float4 a  = reinterpret_cast<const float4*>(h2)[i];
    const float4 b  = reinterpret_cast<const float4*>(sk)[i];
    const float4 s2 = reinterpret_cast<const float4*>(sc2)[c4];
    const float4 t2 = reinterpret_cast<const float4*>(sh2)[c4];
    const float4 sd = reinterpret_cast<const float4*>(scd)[c4];
    const float4 td = reinterpret_cast<const float4*>(shd)[c4];
    float4 v;
    v.x = fmaxf(0.f, fmaf(a.x, s2.x, t2.x) + fmaf(b.x, sd.x, td.x));
    v.y = fmaxf(0.f, fmaf(a.y, s2.y, t2.y) + fmaf(b.y, sd.y, td.y));
    v.z = fmaxf(0.f, fmaf(a.z, s2.z, t2.z) + fmaf(b.z, sd.z, td.z));
    v.w = fmaxf(0.f, fmaf(a.w, s2.w, t2.w) + fmaf(b.w, sd.w, td.w));
    reinterpret_cast<float4*>(out)[i] = v;
}

// ---------------------------------------------------------------------------
extern "C" void kernel_launch(void* const* d_in, const int* in_sizes, int n_in,
                              void* d_out, int out_size)
{
    const float* feats = (const float*)d_in[0];
    const int*   nbr1  = (const int*)  d_in[1];
    const int*   nbr2  = (const int*)  d_in[2];
    const float* W1    = (const float*)d_in[3];
    const float* W2    = (const float*)d_in[4];
    const float* Wd    = (const float*)d_in[5];
    const float* g1    = (const float*)d_in[6];
    const float* b1    = (const float*)d_in[7];
    const float* g2    = (const float*)d_in[8];
    const float* b2    = (const float*)d_in[9];
    const float* gd    = (const float*)d_in[10];
    const float* bd    = (const float*)d_in[11];
    float* out = (float*)d_out;

    const int n  = in_sizes[0] / 64;      // 200000
    const int K  = in_sizes[1] / n;       // 27
    const int nb = (n + ROWS - 1) / ROWS; // 1563

    float *h1, *h2, *sk, *p1, *p2, *pd;
    __half *h1t, *xt;
    uint2 *wp1, *wp2, *wpd;
    float *sc1, *sh1, *sc2, *sh2, *scd, *shd;
    cudaGetSymbolAddress((void**)&h1,  g_h1);
    cudaGetSymbolAddress((void**)&h1t, g_h1t);
    cudaGetSymbolAddress((void**)&h2,  g_h2);
    cudaGetSymbolAddress((void**)&sk,  g_sk);
    cudaGetSymbolAddress((void**)&xt,  g_xt);
    cudaGetSymbolAddress((void**)&wp1, g_wp1);
    cudaGetSymbolAddress((void**)&wp2, g_wp2);
    cudaGetSymbolAddress((void**)&wpd, g_wpd);
    cudaGetSymbolAddress((void**)&p1,  g_part1);
    cudaGetSymbolAddress((void**)&p2,  g_part2);
    cudaGetSymbolAddress((void**)&pd,  g_partd);
    cudaGetSymbolAddress((void**)&sc1, g_sc1);
    cudaGetSymbolAddress((void**)&sh1, g_sh1);
    cudaGetSymbolAddress((void**)&sc2, g_sc2);
    cudaGetSymbolAddress((void**)&sh2, g_sh2);
    cudaGetSymbolAddress((void**)&scd, g_scd);
    cudaGetSymbolAddress((void**)&shd, g_shd);

    const int smem64  = 2 * ROWS * (64 + 8)  * 2;   // 36864 B
    const int smem128 = 2 * ROWS * (128 + 8) * 2;   // 69632 B
    cudaFuncSetAttribute(conv_mma<64>,
        cudaFuncAttributeMaxDynamicSharedMemorySize, smem64);
    cudaFuncSetAttribute(conv_mma<128>,
        cudaFuncAttributeMaxDynamicSharedMemorySize, smem128);

    // ---- prep (ordered so ncu capture at launch index 3 hits conv1) ----
    const int xt8 = n * (64 / 8);
    cvt_h<<<(xt8 + 255) / 256, 256>>>(feats, xt, xt8);               // 0
    {
        int t1 = K * (64 / 16)  * 16 * 32;
        int t2 = K * (128 / 16) * 16 * 32;
        prep_w<<<(t1 + 255) / 256, 256>>>(W1, wp1, K, 64);           // 1
        prep_w<<<(t2 + 255) / 256, 256>>>(W2, wp2, K, 128);          // 2
    }
    // conv1 + BN1 partials                                          // 3
    conv_mma<64><<<nb, NTH, smem64>>>(xt, wp1, nbr1, K, n, h1, p1);
    {
        int td = 1 * (64 / 16) * 16 * 32;
        prep_w<<<(td + 255) / 256, 256>>>(Wd, wpd, 1, 64);
    }
    // skip (identity gather, K=1) + BNd partials
    conv_mma<64><<<nb, NTH, smem64>>>(xt, wpd, nullptr, 1, n, sk, pd);
    bn_finalize<<<128, 256>>>(p1, nb, n, g1, b1, sc1, sh1);
    bn_finalize<<<128, 256>>>(pd, nb, n, gd, bd, scd, shd);
    // h1t = fp16(relu(BN1(h1)))
    const int t8 = n * (COUT / 8);
    bn_relu_cvt_h<<<(t8 + 255) / 256, 256>>>(h1, sc1, sh1, h1t, t8);
    // conv2 + BN2 partials
    conv_mma<128><<<nb, NTH, smem128>>>(h1t, wp2, nbr2, K, n, h2, p2);
    bn_finalize<<<128, 256>>>(p2, nb, n, g2, b2, sc2, sh2);
    // out = relu(BN2(h2) + BNd(sk))
    const int t4 = n * (COUT / 4);
    final_kernel<<<(t4 + 255) / 256, 256>>>(h2, sk, sc2, sh2,
                                            scd, shd, out, t4);
}